// round 5
// baseline (speedup 1.0000x reference)
#include <cuda_runtime.h>
#include <math.h>

#define BB 16
#define Q  8400
#define CC 80
#define G  64
#define RADIUS (2.5f/32.0f)

// ---- scratch (static device globals; no runtime allocation) ----
__device__ float              g_cost[(long long)BB*G*Q];   // [b][g][q]
__device__ unsigned long long g_mask[BB*Q];                // per-anchor GT bitmask
__device__ int                g_rowarg[BB*Q];              // argmin_g cost0[q][g]

// =====================================================================
// Kernel A: warp-per-anchor cost build. Lane l handles g=l and g=l+32.
// Row argmin via shuffle; fg via ballot; coalesced column-major store.
// =====================================================================
#define TBA 512                 // 16 warps = 16 anchors per block
#define QPB 16
__global__ void __launch_bounds__(TBA)
build_cost_kernel(const float* __restrict__ logits,
                  const float* __restrict__ boxes,
                  const int*   __restrict__ labels,
                  const float* __restrict__ gtboxes)
{
    int b = blockIdx.y;
    int qbase = blockIdx.x * QPB;
    int t = threadIdx.x;
    int w = t >> 5, l = t & 31;

    __shared__ float s_gx[G*4];      // gt xyxy
    __shared__ float s_cx[G], s_cy[G], s_area[G];
    __shared__ int   s_lab[G];
    __shared__ float s_cost[G][QPB+1];

    if (t < G) {
        float4 gb = ((const float4*)gtboxes)[b*G + t];
        s_cx[t]=gb.x; s_cy[t]=gb.y;
        float x0=gb.x-0.5f*gb.z, y0=gb.y-0.5f*gb.w;
        float x1=gb.x+0.5f*gb.z, y1=gb.y+0.5f*gb.w;
        s_gx[t*4+0]=x0; s_gx[t*4+1]=y0; s_gx[t*4+2]=x1; s_gx[t*4+3]=y1;
        s_area[t]=(x1-x0)*(y1-y0);
        s_lab[t]=labels[b*G+t];
    }
    __syncthreads();

    int q = qbase + w;
    if (q < Q) {
        float4 pb = ((const float4*)boxes)[b*Q + q];
        float ax = pb.x, ay = pb.y;
        float bx0 = pb.x-0.5f*pb.z, by0 = pb.y-0.5f*pb.w;
        float bx1 = pb.x+0.5f*pb.z, by1 = pb.y+0.5f*pb.w;
        float areaA = (bx1-bx0)*(by1-by0);
        const float* lrow = logits + ((long long)b*Q + q)*CC;

        float costv[2];
        bool  anyflag = false;
        bool  iibcv[2];

        // geometry + iibc + fg flags for this lane's two g's
        #pragma unroll
        for (int h=0; h<2; h++) {
            int g = l + h*32;
            bool ib = (ax>s_gx[g*4+0]) && (ax<s_gx[g*4+2]) &&
                      (ay>s_gx[g*4+1]) && (ay<s_gx[g*4+3]);
            bool ic = (ax>s_cx[g]-RADIUS)&&(ax<s_cx[g]+RADIUS)&&
                      (ay>s_cy[g]-RADIUS)&&(ay<s_cy[g]+RADIUS);
            anyflag |= (ib | ic);
            iibcv[h] = ib && ic;
        }
        unsigned ball = __ballot_sync(0xffffffffu, anyflag);
        float fgterm = ball ? 0.0f : 10000.0f;

        #pragma unroll
        for (int h=0; h<2; h++) {
            int g = l + h*32;
            float x = __ldg(lrow + s_lab[g]);
            float p = 1.0f/(1.0f + expf(-x));
            float neg = 0.75f * p*p * (-logf(1.0f - p + 1e-8f));
            float pos = 0.25f * (1.0f-p)*(1.0f-p) * (-logf(p + 1e-8f));
            float cls = pos - neg;

            float gx0=s_gx[g*4+0], gy0=s_gx[g*4+1], gx1=s_gx[g*4+2], gy1=s_gx[g*4+3];
            float ltx=fmaxf(bx0,gx0), lty=fmaxf(by0,gy0);
            float rbx=fminf(bx1,gx1), rby=fminf(by1,gy1);
            float iw=fmaxf(rbx-ltx,0.0f), ih=fmaxf(rby-lty,0.0f);
            float inter = iw*ih;
            float uni   = areaA + s_area[g] - inter;
            float iou   = inter/uni;
            float ex0=fminf(bx0,gx0), ey0=fminf(by0,gy0);
            float ex1=fmaxf(bx1,gx1), ey1=fmaxf(by1,gy1);
            float encl = fmaxf(ex1-ex0,0.0f)*fmaxf(ey1-ey0,0.0f);
            float giou = iou - (encl - uni)/encl;

            costv[h] = cls - 3.0f*giou + (iibcv[h] ? 0.0f : 100.0f) + fgterm;
            s_cost[g][w] = costv[h];
        }

        // warp row-argmin (lowest g on ties)
        float bv; int bg;
        if (costv[1] < costv[0]) { bv = costv[1]; bg = l+32; }
        else                     { bv = costv[0]; bg = l;    }
        #pragma unroll
        for (int off=16; off; off>>=1) {
            float ov = __shfl_down_sync(0xffffffffu, bv, off);
            int   og = __shfl_down_sync(0xffffffffu, bg, off);
            if (ov < bv || (ov==bv && og < bg)) { bv=ov; bg=og; }
        }
        if (l==0) {
            g_rowarg[b*Q+q] = bg;
            g_mask  [b*Q+q] = 0ULL;
        }
    }
    __syncthreads();

    // coalesced column-major store: g_cost[b][g][qbase..qbase+15]
    int r0 = t >> 4, j = t & 15;
    int qq = qbase + j;
    if (qq < Q) {
        #pragma unroll
        for (int r = r0; r < G; r += TBA/16)
            g_cost[((long long)b*G + r)*Q + qq] = s_cost[r][j];
    }
}

// =====================================================================
// Kernel B: per (b,g) column, SINGLE pass: recompute iou from boxes,
// maintain top-10 iou + bottom-10 (cost,idx) lex; dyn_k; set mask bits.
// =====================================================================
#define TKB 256
__global__ void __launch_bounds__(TKB)
select_kernel(const float* __restrict__ boxes,
              const float* __restrict__ gtboxes)
{
    int b = blockIdx.x >> 6, g = blockIdx.x & 63;
    const float* cost = g_cost + ((long long)b*G+g)*Q;
    const float4* abox = (const float4*)boxes + (long long)b*Q;
    int t = threadIdx.x;

    // gt box for this column (registers, identical op order as build)
    float4 gb = __ldg(&((const float4*)gtboxes)[b*G+g]);
    float gx0=gb.x-0.5f*gb.z, gy0=gb.y-0.5f*gb.w;
    float gx1=gb.x+0.5f*gb.z, gy1=gb.y+0.5f*gb.w;
    float areaG=(gx1-gx0)*(gy1-gy0);

    __shared__ float s_pv[TKB*10];
    __shared__ int   s_pi[TKB*10];
    __shared__ int   s_dynk;

    float itop[10];
    float pv[10]; int pi[10];
    #pragma unroll
    for (int i=0;i<10;i++) { itop[i]=-INFINITY; pv[i]=INFINITY; pi[i]=0x7FFFFFFF; }

    for (int q=t; q<Q; q+=TKB) {
        float4 pb = abox[q];
        float bx0 = pb.x-0.5f*pb.z, by0 = pb.y-0.5f*pb.w;
        float bx1 = pb.x+0.5f*pb.z, by1 = pb.y+0.5f*pb.w;
        float areaA = (bx1-bx0)*(by1-by0);
        float ltx=fmaxf(bx0,gx0), lty=fmaxf(by0,gy0);
        float rbx=fminf(bx1,gx1), rby=fminf(by1,gy1);
        float iw=fmaxf(rbx-ltx,0.0f), ih=fmaxf(rby-lty,0.0f);
        float inter = iw*ih;
        float uni   = areaA + areaG - inter;
        float iou   = inter/uni;

        if (iou > itop[9]) {
            int i = 9;
            while (i>0 && itop[i-1] < iou) { itop[i]=itop[i-1]; i--; }
            itop[i] = iou;
        }
        float v = cost[q];
        if (v < pv[9]) {
            int i = 9;
            while (i>0 && v < pv[i-1]) { pv[i]=pv[i-1]; pi[i]=pi[i-1]; i--; }
            pv[i]=v; pi[i]=q;
        }
    }

    // ---- merge iou top-10 (descending) ----
    #pragma unroll
    for (int i=0;i<10;i++) s_pv[t*10+i] = itop[i];
    __syncthreads();
    for (int s=TKB/2; s>=1; s>>=1) {
        if (t < s) {
            float a[10], c[10], m[10];
            #pragma unroll
            for (int i=0;i<10;i++){ a[i]=s_pv[t*10+i]; c[i]=s_pv[(t+s)*10+i]; }
            int ia=0, ic=0;
            #pragma unroll
            for (int i=0;i<10;i++) m[i] = (a[ia] >= c[ic]) ? a[ia++] : c[ic++];
            #pragma unroll
            for (int i=0;i<10;i++) s_pv[t*10+i] = m[i];
        }
        __syncthreads();
    }
    if (t==0) {
        float ssum = 0.0f;
        for (int i=0;i<10;i++) ssum += s_pv[i];
        int k = (int)ssum;
        if (k < 1) k = 1;
        if (k > 10) k = 10;
        s_dynk = k;
    }
    __syncthreads();

    // ---- merge (cost,idx) bottom-10 lex ----
    #pragma unroll
    for (int i=0;i<10;i++) { s_pv[t*10+i]=pv[i]; s_pi[t*10+i]=pi[i]; }
    __syncthreads();
    for (int s=TKB/2; s>=1; s>>=1) {
        if (t < s) {
            float av[10], bv[10], mv[10];
            int   ai[10], bi[10], mi[10];
            #pragma unroll
            for (int i=0;i<10;i++){
                av[i]=s_pv[t*10+i];     ai[i]=s_pi[t*10+i];
                bv[i]=s_pv[(t+s)*10+i]; bi[i]=s_pi[(t+s)*10+i];
            }
            int ia=0, ic=0;
            #pragma unroll
            for (int i=0;i<10;i++) {
                bool takeA = (av[ia] < bv[ic]) ||
                             (av[ia]==bv[ic] && ai[ia] < bi[ic]);
                if (takeA) { mv[i]=av[ia]; mi[i]=ai[ia]; ia++; }
                else       { mv[i]=bv[ic]; mi[i]=bi[ic]; ic++; }
            }
            #pragma unroll
            for (int i=0;i<10;i++){ s_pv[t*10+i]=mv[i]; s_pi[t*10+i]=mi[i]; }
        }
        __syncthreads();
    }
    if (t==0) {
        int k = s_dynk;
        for (int j=0; j<k; j++)
            atomicOr(&g_mask[b*Q + s_pi[j]], 1ULL<<g);
    }
}

// =====================================================================
// Kernel C: per-image dedup + while-loop + outputs; state in dyn smem.
// =====================================================================
#define TD 1024
#define NW (TD/32)
#define NWORD ((Q+31)/32)
#define SMEM_LOOP (Q*8 + Q*4 + NWORD*4 + 16)
__global__ void __launch_bounds__(TD)
loop_kernel(char* __restrict__ out_bytes, int layoutB)
{
    extern __shared__ char sm[];
    unsigned long long* smask = (unsigned long long*)sm;      // Q
    float*    span   = (float*)(sm + (size_t)Q*8);            // Q
    unsigned* sstale = (unsigned*)(sm + (size_t)Q*8 + (size_t)Q*4); // NWORD

    int b = blockIdx.x, t = threadIdx.x;
    int wid = t/32, lane = t%32;
    const float* cost = g_cost + (long long)b*G*Q;
    const int*   rowarg = g_rowarg + b*Q;

    __shared__ int s_cnt[G];
    __shared__ int s_unm[G];
    __shared__ int s_n;
    __shared__ int s_fix;

    for (int i=t; i<NWORD; i+=TD) sstale[i] = 0u;
    __syncthreads();

    // prologue: dedup rows with >1 matches -> one-hot(rowarg); mark stale
    for (int q=t; q<Q; q+=TD) {
        unsigned long long m = g_mask[b*Q+q];
        if (__popcll(m) > 1) {
            m = 1ULL << rowarg[q];
            atomicOr(&sstale[q>>5], 1u << (q&31));
        }
        smask[q] = m;
        span[q]  = 0.0f;
    }
    __syncthreads();

    for (int iter=0; iter<20000; iter++) {
        if (t < G) s_cnt[t] = 0;
        if (t == 0) { s_n = 0; s_fix = 0; }
        __syncthreads();
        for (int q=t; q<Q; q+=TD) {
            unsigned long long m = smask[q];
            while (m) { int g = __ffsll((long long)m)-1; atomicAdd(&s_cnt[g],1); m &= m-1; }
        }
        __syncthreads();
        if (t < G && s_cnt[t] == 0) s_unm[atomicAdd(&s_n,1)] = t;
        __syncthreads();
        if (s_n == 0) break;

        for (int q=t; q<Q; q+=TD) if (smask[q]) span[q] += 100000.0f;
        __syncthreads();

        // warp-parallel column argmins over unmatched columns
        for (int u = wid; u < s_n; u += NW) {
            int g = s_unm[u];
            const float* cg = cost + (long long)g*Q;
            float bv = INFINITY; int bi = Q;
            for (int q=lane; q<Q; q+=32) {
                float v = cg[q] + span[q];
                if (v < bv) { bv=v; bi=q; }
            }
            #pragma unroll
            for (int off=16; off; off>>=1) {
                float ov = __shfl_down_sync(0xffffffffu, bv, off);
                int   oi = __shfl_down_sync(0xffffffffu, bi, off);
                if (ov < bv || (ov==bv && oi < bi)) { bv=ov; bi=oi; }
            }
            if (lane==0) atomicOr(&smask[bi], 1ULL<<g);
        }
        __syncthreads();

        for (int q=t; q<Q; q+=TD) if (__popcll(smask[q]) > 1) s_fix = 1;
        __syncthreads();
        if (s_fix) {
            for (int q=t; q<Q; q+=TD)
                if ((sstale[q>>5] >> (q&31)) & 1u)
                    smask[q] = 1ULL << rowarg[q];
        }
        __syncthreads();
    }

    // ---- outputs ----
    if (layoutB) {
        unsigned char* out_sel = (unsigned char*)out_bytes;
        int* out_asn = (int*)(out_bytes + (size_t)BB*Q);
        int* out_mq  = (int*)(out_bytes + (size_t)BB*Q + (size_t)4*BB*Q);
        for (int q=t; q<Q; q+=TD) {
            unsigned long long m = smask[q];
            out_sel[b*Q+q] = m ? 1 : 0;
            out_asn[b*Q+q] = m ? (__ffsll((long long)m)-1) : 0;
        }
        for (int g=wid; g<G; g+=NW) {
            const float* cg = cost + (long long)g*Q;
            float bv = INFINITY; int bi = 0;
            for (int q=lane; q<Q; q+=32) {
                if ((smask[q]>>g) & 1ULL) {
                    float v = cg[q] + span[q];
                    if (v < bv) { bv=v; bi=q; }
                }
            }
            #pragma unroll
            for (int off=16; off; off>>=1) {
                float ov = __shfl_down_sync(0xffffffffu, bv, off);
                int   oi = __shfl_down_sync(0xffffffffu, bi, off);
                if (ov < bv || (ov==bv && oi < bi)) { bv=ov; bi=oi; }
            }
            if (lane==0) out_mq[b*G+g] = bi;
        }
    } else {
        float* out = (float*)out_bytes;
        float* out_sel = out;
        float* out_asn = out + BB*Q;
        float* out_mq  = out + 2*BB*Q;
        for (int q=t; q<Q; q+=TD) {
            unsigned long long m = smask[q];
            out_sel[b*Q+q] = m ? 1.0f : 0.0f;
            out_asn[b*Q+q] = m ? (float)(__ffsll((long long)m)-1) : 0.0f;
        }
        for (int g=wid; g<G; g+=NW) {
            const float* cg = cost + (long long)g*Q;
            float bv = INFINITY; int bi = 0;
            for (int q=lane; q<Q; q+=32) {
                if ((smask[q]>>g) & 1ULL) {
                    float v = cg[q] + span[q];
                    if (v < bv) { bv=v; bi=q; }
                }
            }
            #pragma unroll
            for (int off=16; off; off>>=1) {
                float ov = __shfl_down_sync(0xffffffffu, bv, off);
                int   oi = __shfl_down_sync(0xffffffffu, bi, off);
                if (ov < bv || (ov==bv && oi < bi)) { bv=ov; bi=oi; }
            }
            if (lane==0) out_mq[b*G+g] = (float)bi;
        }
    }
}

// =====================================================================
extern "C" void kernel_launch(void* const* d_in, const int* in_sizes, int n_in,
                              void* d_out, int out_size)
{
    const float* logits = 0; const float* boxes = 0;
    const int*   labels = 0; const float* gtb   = 0;
    for (int i = 0; i < n_in; i++) {
        switch (in_sizes[i]) {
            case BB*Q*CC: logits = (const float*)d_in[i]; break;
            case BB*Q*4:  boxes  = (const float*)d_in[i]; break;
            case BB*G:    labels = (const int*)  d_in[i]; break;
            case BB*G*4:  gtb    = (const float*)d_in[i]; break;
        }
    }

    int layoutB = (out_size == BB*Q + 4*BB*Q + 4*BB*G) ? 1 : 0;

    static int smem_set = 0;
    if (!smem_set) {
        cudaFuncSetAttribute(loop_kernel,
                             cudaFuncAttributeMaxDynamicSharedMemorySize,
                             SMEM_LOOP);
        smem_set = 1;
    }

    dim3 gA((Q + QPB - 1)/QPB, BB);
    build_cost_kernel<<<gA, TBA>>>(logits, boxes, labels, gtb);
    select_kernel<<<BB*G, TKB>>>(boxes, gtb);
    loop_kernel<<<BB, TD, SMEM_LOOP>>>((char*)d_out, layoutB);
}

// round 6
// speedup vs baseline: 1.7114x; 1.7114x over previous
#include <cuda_runtime.h>
#include <math.h>

#define BB 16
#define Q  8400
#define CC 80
#define G  64
#define RADIUS (2.5f/32.0f)

// ---- scratch (static device globals; no runtime allocation) ----
__device__ float              g_cost[(long long)BB*G*Q];   // [b][g][q]
__device__ unsigned long long g_mask[BB*Q];                // per-anchor GT bitmask
__device__ int                g_rowarg[BB*Q];              // argmin_g cost0[q][g]

// =====================================================================
// Kernel A: warp-per-anchor cost build. Lane l handles g=l and g=l+32.
// =====================================================================
#define TBA 512
#define QPB 16
__global__ void __launch_bounds__(TBA)
build_cost_kernel(const float* __restrict__ logits,
                  const float* __restrict__ boxes,
                  const int*   __restrict__ labels,
                  const float* __restrict__ gtboxes)
{
    int b = blockIdx.y;
    int qbase = blockIdx.x * QPB;
    int t = threadIdx.x;
    int w = t >> 5, l = t & 31;

    __shared__ float s_gx[G*4];
    __shared__ float s_cx[G], s_cy[G], s_area[G];
    __shared__ int   s_lab[G];
    __shared__ float s_cost[G][QPB+1];

    if (t < G) {
        float4 gb = ((const float4*)gtboxes)[b*G + t];
        s_cx[t]=gb.x; s_cy[t]=gb.y;
        float x0=gb.x-0.5f*gb.z, y0=gb.y-0.5f*gb.w;
        float x1=gb.x+0.5f*gb.z, y1=gb.y+0.5f*gb.w;
        s_gx[t*4+0]=x0; s_gx[t*4+1]=y0; s_gx[t*4+2]=x1; s_gx[t*4+3]=y1;
        s_area[t]=(x1-x0)*(y1-y0);
        s_lab[t]=labels[b*G+t];
    }
    __syncthreads();

    int q = qbase + w;
    if (q < Q) {
        float4 pb = ((const float4*)boxes)[b*Q + q];
        float ax = pb.x, ay = pb.y;
        float bx0 = pb.x-0.5f*pb.z, by0 = pb.y-0.5f*pb.w;
        float bx1 = pb.x+0.5f*pb.z, by1 = pb.y+0.5f*pb.w;
        float areaA = (bx1-bx0)*(by1-by0);
        const float* lrow = logits + ((long long)b*Q + q)*CC;

        float costv[2];
        bool  anyflag = false;
        bool  iibcv[2];

        #pragma unroll
        for (int h=0; h<2; h++) {
            int g = l + h*32;
            bool ib = (ax>s_gx[g*4+0]) && (ax<s_gx[g*4+2]) &&
                      (ay>s_gx[g*4+1]) && (ay<s_gx[g*4+3]);
            bool ic = (ax>s_cx[g]-RADIUS)&&(ax<s_cx[g]+RADIUS)&&
                      (ay>s_cy[g]-RADIUS)&&(ay<s_cy[g]+RADIUS);
            anyflag |= (ib | ic);
            iibcv[h] = ib && ic;
        }
        unsigned ball = __ballot_sync(0xffffffffu, anyflag);
        float fgterm = ball ? 0.0f : 10000.0f;

        #pragma unroll
        for (int h=0; h<2; h++) {
            int g = l + h*32;
            float x = __ldg(lrow + s_lab[g]);
            float p = 1.0f/(1.0f + expf(-x));
            float neg = 0.75f * p*p * (-logf(1.0f - p + 1e-8f));
            float pos = 0.25f * (1.0f-p)*(1.0f-p) * (-logf(p + 1e-8f));
            float cls = pos - neg;

            float gx0=s_gx[g*4+0], gy0=s_gx[g*4+1], gx1=s_gx[g*4+2], gy1=s_gx[g*4+3];
            float ltx=fmaxf(bx0,gx0), lty=fmaxf(by0,gy0);
            float rbx=fminf(bx1,gx1), rby=fminf(by1,gy1);
            float iw=fmaxf(rbx-ltx,0.0f), ih=fmaxf(rby-lty,0.0f);
            float inter = iw*ih;
            float uni   = areaA + s_area[g] - inter;
            float iou   = inter/uni;
            float ex0=fminf(bx0,gx0), ey0=fminf(by0,gy0);
            float ex1=fmaxf(bx1,gx1), ey1=fmaxf(by1,gy1);
            float encl = fmaxf(ex1-ex0,0.0f)*fmaxf(ey1-ey0,0.0f);
            float giou = iou - (encl - uni)/encl;

            costv[h] = cls - 3.0f*giou + (iibcv[h] ? 0.0f : 100.0f) + fgterm;
            s_cost[g][w] = costv[h];
        }

        float bv; int bg;
        if (costv[1] < costv[0]) { bv = costv[1]; bg = l+32; }
        else                     { bv = costv[0]; bg = l;    }
        #pragma unroll
        for (int off=16; off; off>>=1) {
            float ov = __shfl_down_sync(0xffffffffu, bv, off);
            int   og = __shfl_down_sync(0xffffffffu, bg, off);
            if (ov < bv || (ov==bv && og < bg)) { bv=ov; bg=og; }
        }
        if (l==0) {
            g_rowarg[b*Q+q] = bg;
            g_mask  [b*Q+q] = 0ULL;
        }
    }
    __syncthreads();

    int r0 = t >> 4, j = t & 15;
    int qq = qbase + j;
    if (qq < Q) {
        #pragma unroll
        for (int r = r0; r < G; r += TBA/16)
            g_cost[((long long)b*G + r)*Q + qq] = s_cost[r][j];
    }
}

// =====================================================================
// Kernel B: per (b,g) column, single pass; REGISTER-RESIDENT lists
// (static-index swap chains, no local-memory spills).
// =====================================================================
#define TKB 256
__global__ void __launch_bounds__(TKB)
select_kernel(const float* __restrict__ boxes,
              const float* __restrict__ gtboxes)
{
    int b = blockIdx.x >> 6, g = blockIdx.x & 63;
    const float* cost = g_cost + ((long long)b*G+g)*Q;
    const float4* abox = (const float4*)boxes + (long long)b*Q;
    int t = threadIdx.x;

    float4 gb = __ldg(&((const float4*)gtboxes)[b*G+g]);
    float gx0=gb.x-0.5f*gb.z, gy0=gb.y-0.5f*gb.w;
    float gx1=gb.x+0.5f*gb.z, gy1=gb.y+0.5f*gb.w;
    float areaG=(gx1-gx0)*(gy1-gy0);

    __shared__ float s_pv[TKB*10];
    __shared__ int   s_pi[TKB*10];
    __shared__ int   s_dynk;

    float itop[10];
    float pv[10]; int pi[10];
    #pragma unroll
    for (int i=0;i<10;i++) { itop[i]=-INFINITY; pv[i]=INFINITY; pi[i]=0x7FFFFFFF; }

    for (int q=t; q<Q; q+=TKB) {
        float4 pb = __ldg(abox + q);
        float bx0 = pb.x-0.5f*pb.z, by0 = pb.y-0.5f*pb.w;
        float bx1 = pb.x+0.5f*pb.z, by1 = pb.y+0.5f*pb.w;
        float areaA = (bx1-bx0)*(by1-by0);
        float ltx=fmaxf(bx0,gx0), lty=fmaxf(by0,gy0);
        float rbx=fminf(bx1,gx1), rby=fminf(by1,gy1);
        float iw=fmaxf(rbx-ltx,0.0f), ih=fmaxf(rby-lty,0.0f);
        float inter = iw*ih;
        float uni   = areaA + areaG - inter;
        float iou   = inter/uni;

        // descending top-10 via unrolled swap chain (registers only)
        if (iou > itop[9]) {
            float nv = iou;
            #pragma unroll
            for (int i=0;i<10;i++) {
                float cur = itop[i];
                bool take = nv > cur;
                itop[i] = take ? nv : cur;
                nv      = take ? cur : nv;
            }
        }

        float v = cost[q];
        // ascending (value,idx)-lex bottom-10 via unrolled swap chain
        if (v < pv[9]) {
            float nv = v; int ni = q;
            #pragma unroll
            for (int i=0;i<10;i++) {
                float cv = pv[i]; int ci = pi[i];
                bool take = (nv < cv) || (nv == cv && ni < ci);
                pv[i] = take ? nv : cv;  pi[i] = take ? ni : ci;
                nv    = take ? cv : nv;  ni    = take ? ci : ni;
            }
        }
    }

    // ---- merge iou top-10 (descending) ----
    #pragma unroll
    for (int i=0;i<10;i++) s_pv[t*10+i] = itop[i];
    __syncthreads();
    for (int s=TKB/2; s>=1; s>>=1) {
        if (t < s) {
            float a[10], c[10], m[10];
            #pragma unroll
            for (int i=0;i<10;i++){ a[i]=s_pv[t*10+i]; c[i]=s_pv[(t+s)*10+i]; }
            int ia=0, ic=0;
            #pragma unroll
            for (int i=0;i<10;i++) m[i] = (a[ia] >= c[ic]) ? a[ia++] : c[ic++];
            #pragma unroll
            for (int i=0;i<10;i++) s_pv[t*10+i] = m[i];
        }
        __syncthreads();
    }
    if (t==0) {
        float ssum = 0.0f;
        for (int i=0;i<10;i++) ssum += s_pv[i];
        int k = (int)ssum;
        if (k < 1) k = 1;
        if (k > 10) k = 10;
        s_dynk = k;
    }
    __syncthreads();

    // ---- merge (cost,idx) bottom-10 lex ----
    #pragma unroll
    for (int i=0;i<10;i++) { s_pv[t*10+i]=pv[i]; s_pi[t*10+i]=pi[i]; }
    __syncthreads();
    for (int s=TKB/2; s>=1; s>>=1) {
        if (t < s) {
            float av[10], bv[10], mv[10];
            int   ai[10], bi[10], mi[10];
            #pragma unroll
            for (int i=0;i<10;i++){
                av[i]=s_pv[t*10+i];     ai[i]=s_pi[t*10+i];
                bv[i]=s_pv[(t+s)*10+i]; bi[i]=s_pi[(t+s)*10+i];
            }
            int ia=0, ic=0;
            #pragma unroll
            for (int i=0;i<10;i++) {
                bool takeA = (av[ia] < bv[ic]) ||
                             (av[ia]==bv[ic] && ai[ia] < bi[ic]);
                if (takeA) { mv[i]=av[ia]; mi[i]=ai[ia]; ia++; }
                else       { mv[i]=bv[ic]; mi[i]=bi[ic]; ic++; }
            }
            #pragma unroll
            for (int i=0;i<10;i++){ s_pv[t*10+i]=mv[i]; s_pi[t*10+i]=mi[i]; }
        }
        __syncthreads();
    }
    if (t==0) {
        int k = s_dynk;
        for (int j=0; j<k; j++)
            atomicOr(&g_mask[b*Q + s_pi[j]], 1ULL<<g);
    }
}

// =====================================================================
// Kernel C: per-image dedup + while-loop + outputs; state in dyn smem;
// argmin scans vectorized float4.
// =====================================================================
#define TD 1024
#define NW (TD/32)
#define NWORD ((Q+31)/32)
#define Q4 (Q/4)
#define SMEM_LOOP (Q*8 + Q*4 + NWORD*4 + 16)
__global__ void __launch_bounds__(TD)
loop_kernel(char* __restrict__ out_bytes, int layoutB)
{
    extern __shared__ char sm[];
    unsigned long long* smask = (unsigned long long*)sm;                 // Q
    float*    span   = (float*)(sm + (size_t)Q*8);                       // Q
    unsigned* sstale = (unsigned*)(sm + (size_t)Q*8 + (size_t)Q*4);      // NWORD
    const float4* span4 = (const float4*)span;

    int b = blockIdx.x, t = threadIdx.x;
    int wid = t/32, lane = t%32;
    const float* cost = g_cost + (long long)b*G*Q;
    const int*   rowarg = g_rowarg + b*Q;

    __shared__ int s_cnt[G];
    __shared__ int s_unm[G];
    __shared__ int s_n;
    __shared__ int s_fix;

    for (int i=t; i<NWORD; i+=TD) sstale[i] = 0u;
    __syncthreads();

    for (int q=t; q<Q; q+=TD) {
        unsigned long long m = g_mask[b*Q+q];
        if (__popcll(m) > 1) {
            m = 1ULL << rowarg[q];
            atomicOr(&sstale[q>>5], 1u << (q&31));
        }
        smask[q] = m;
        span[q]  = 0.0f;
    }
    __syncthreads();

    for (int iter=0; iter<20000; iter++) {
        if (t < G) s_cnt[t] = 0;
        if (t == 0) { s_n = 0; s_fix = 0; }
        __syncthreads();
        for (int q=t; q<Q; q+=TD) {
            unsigned long long m = smask[q];
            while (m) { int g = __ffsll((long long)m)-1; atomicAdd(&s_cnt[g],1); m &= m-1; }
        }
        __syncthreads();
        if (t < G && s_cnt[t] == 0) s_unm[atomicAdd(&s_n,1)] = t;
        __syncthreads();
        if (s_n == 0) break;

        for (int q=t; q<Q; q+=TD) if (smask[q]) span[q] += 100000.0f;
        __syncthreads();

        // warp-parallel vectorized column argmins over unmatched columns
        for (int u = wid; u < s_n; u += NW) {
            int g = s_unm[u];
            const float4* cg4 = (const float4*)(cost + (long long)g*Q);
            float bv = INFINITY; int bi = Q;
            #pragma unroll 4
            for (int i = lane; i < Q4; i += 32) {
                float4 c = __ldg(cg4 + i);
                float4 s = span4[i];
                int q0 = i*4;
                float v0 = c.x + s.x; if (v0 < bv) { bv=v0; bi=q0;   }
                float v1 = c.y + s.y; if (v1 < bv) { bv=v1; bi=q0+1; }
                float v2 = c.z + s.z; if (v2 < bv) { bv=v2; bi=q0+2; }
                float v3 = c.w + s.w; if (v3 < bv) { bv=v3; bi=q0+3; }
            }
            #pragma unroll
            for (int off=16; off; off>>=1) {
                float ov = __shfl_down_sync(0xffffffffu, bv, off);
                int   oi = __shfl_down_sync(0xffffffffu, bi, off);
                if (ov < bv || (ov==bv && oi < bi)) { bv=ov; bi=oi; }
            }
            if (lane==0) atomicOr(&smask[bi], 1ULL<<g);
        }
        __syncthreads();

        for (int q=t; q<Q; q+=TD) if (__popcll(smask[q]) > 1) s_fix = 1;
        __syncthreads();
        if (s_fix) {
            for (int q=t; q<Q; q+=TD)
                if ((sstale[q>>5] >> (q&31)) & 1u)
                    smask[q] = 1ULL << rowarg[q];
        }
        __syncthreads();
    }

    // ---- outputs ----
    if (layoutB) {
        unsigned char* out_sel = (unsigned char*)out_bytes;
        int* out_asn = (int*)(out_bytes + (size_t)BB*Q);
        int* out_mq  = (int*)(out_bytes + (size_t)BB*Q + (size_t)4*BB*Q);
        for (int q=t; q<Q; q+=TD) {
            unsigned long long m = smask[q];
            out_sel[b*Q+q] = m ? 1 : 0;
            out_asn[b*Q+q] = m ? (__ffsll((long long)m)-1) : 0;
        }
        for (int g=wid; g<G; g+=NW) {
            const float* cg = cost + (long long)g*Q;
            float bv = INFINITY; int bi = 0;
            for (int q=lane; q<Q; q+=32) {
                if ((smask[q]>>g) & 1ULL) {
                    float v = cg[q] + span[q];
                    if (v < bv) { bv=v; bi=q; }
                }
            }
            #pragma unroll
            for (int off=16; off; off>>=1) {
                float ov = __shfl_down_sync(0xffffffffu, bv, off);
                int   oi = __shfl_down_sync(0xffffffffu, bi, off);
                if (ov < bv || (ov==bv && oi < bi)) { bv=ov; bi=oi; }
            }
            if (lane==0) out_mq[b*G+g] = bi;
        }
    } else {
        float* out = (float*)out_bytes;
        float* out_sel = out;
        float* out_asn = out + BB*Q;
        float* out_mq  = out + 2*BB*Q;
        for (int q=t; q<Q; q+=TD) {
            unsigned long long m = smask[q];
            out_sel[b*Q+q] = m ? 1.0f : 0.0f;
            out_asn[b*Q+q] = m ? (float)(__ffsll((long long)m)-1) : 0.0f;
        }
        for (int g=wid; g<G; g+=NW) {
            const float* cg = cost + (long long)g*Q;
            float bv = INFINITY; int bi = 0;
            for (int q=lane; q<Q; q+=32) {
                if ((smask[q]>>g) & 1ULL) {
                    float v = cg[q] + span[q];
                    if (v < bv) { bv=v; bi=q; }
                }
            }
            #pragma unroll
            for (int off=16; off; off>>=1) {
                float ov = __shfl_down_sync(0xffffffffu, bv, off);
                int   oi = __shfl_down_sync(0xffffffffu, bi, off);
                if (ov < bv || (ov==bv && oi < bi)) { bv=ov; bi=oi; }
            }
            if (lane==0) out_mq[b*G+g] = (float)bi;
        }
    }
}

// =====================================================================
extern "C" void kernel_launch(void* const* d_in, const int* in_sizes, int n_in,
                              void* d_out, int out_size)
{
    const float* logits = 0; const float* boxes = 0;
    const int*   labels = 0; const float* gtb   = 0;
    for (int i = 0; i < n_in; i++) {
        switch (in_sizes[i]) {
            case BB*Q*CC: logits = (const float*)d_in[i]; break;
            case BB*Q*4:  boxes  = (const float*)d_in[i]; break;
            case BB*G:    labels = (const int*)  d_in[i]; break;
            case BB*G*4:  gtb    = (const float*)d_in[i]; break;
        }
    }

    int layoutB = (out_size == BB*Q + 4*BB*Q + 4*BB*G) ? 1 : 0;

    static int smem_set = 0;
    if (!smem_set) {
        cudaFuncSetAttribute(loop_kernel,
                             cudaFuncAttributeMaxDynamicSharedMemorySize,
                             SMEM_LOOP);
        smem_set = 1;
    }

    dim3 gA((Q + QPB - 1)/QPB, BB);
    build_cost_kernel<<<gA, TBA>>>(logits, boxes, labels, gtb);
    select_kernel<<<BB*G, TKB>>>(boxes, gtb);
    loop_kernel<<<BB, TD, SMEM_LOOP>>>((char*)d_out, layoutB);
}